// round 1
// baseline (speedup 1.0000x reference)
#include <cuda_runtime.h>

#define HH 56
#define WW 56
#define HWP 3136
#define CGC 16
#define NGRP 1024
#define NT 512
#define EPSV 1e-5f

// smem float offsets (all multiples of 4 for float4 access)
#define OFF_SX   0
#define OFF_XH   50176
#define OFF_XW   51072
#define OFF_RS   51968
#define OFF_CS   52864
#define OFF_W1   53760
#define OFF_W3   54016
#define OFF_WC   56320
#define OFF_SA   56464
#define OFF_B1   56608
#define OFF_B3   56624
#define OFF_GNW  56640
#define OFF_GNB  56656
#define OFF_MU   56672
#define OFF_SS   56688
#define OFF_TT   56704
#define OFF_M2   56720
#define OFF_A1   56736
#define OFF_A2C  56752
#define OFF_CONST 56768
#define SMEM_FLOATS 56776
#define SMEM_BYTES (SMEM_FLOATS * 4)

__device__ __forceinline__ float wred(float v) {
#pragma unroll
    for (int o = 16; o; o >>= 1) v += __shfl_down_sync(0xffffffffu, v, o);
    return v;
}
__device__ __forceinline__ float sigm(float z) { return 1.f / (1.f + __expf(-z)); }

__global__ __launch_bounds__(NT, 1)
void ema_fused_kernel(const float* __restrict__ x,
                      const float* __restrict__ w1, const float* __restrict__ b1,
                      const float* __restrict__ w3, const float* __restrict__ b3,
                      const float* __restrict__ gnw, const float* __restrict__ gnb,
                      float* __restrict__ out) {
    extern __shared__ float sm[];
    float* SX  = sm + OFF_SX;
    float* XH  = sm + OFF_XH;
    float* XW  = sm + OFF_XW;
    float* RS  = sm + OFF_RS;
    float* CS  = sm + OFF_CS;
    float* W1s = sm + OFF_W1;
    float* W3s = sm + OFF_W3;
    float* WC  = sm + OFF_WC;
    float* SA  = sm + OFF_SA;
    float* B1s = sm + OFF_B1;
    float* B3s = sm + OFF_B3;
    float* GNWs = sm + OFF_GNW;
    float* GNBs = sm + OFF_GNB;
    float* MU  = sm + OFF_MU;
    float* SSv = sm + OFF_SS;
    float* TT  = sm + OFF_TT;
    float* M2  = sm + OFF_M2;
    float* A1v = sm + OFF_A1;
    float* A2C = sm + OFF_A2C;
    float* CONSTS = sm + OFF_CONST;

    const int tid = threadIdx.x;
    const int g = blockIdx.x;
    const float* gx = x + (size_t)g * (CGC * HWP);
    float* og = out + (size_t)g * (CGC * HWP);

    // ---- Phase 0: load tile + params into SMEM ----
    {
        const float4* gx4 = (const float4*)gx;
        float4* sx4 = (float4*)SX;
#pragma unroll 4
        for (int i = tid; i < (CGC * HWP) / 4; i += NT) sx4[i] = gx4[i];
        for (int i = tid; i < 2304; i += NT) W3s[i] = w3[i];
        if (tid < 256) W1s[tid] = w1[tid];
        if (tid < 16) {
            B1s[tid] = b1[tid]; B3s[tid] = b3[tid];
            GNWs[tid] = gnw[tid]; GNBs[tid] = gnb[tid];
        }
    }
    __syncthreads();

    const int warp = tid >> 5;
    const int lane = tid & 31;

    // ---- Phase 1a: row sums RS[c*56+h] (warp per row) ----
    for (int r = warp; r < CGC * HH; r += 16) {
        int c = r / HH, h = r - c * HH;
        int base = c * HWP + h * WW;
        float v = SX[base + lane];
        if (lane < 24) v += SX[base + lane + 32];
        v = wred(v);
        if (lane == 0) RS[r] = v;
    }
    // ---- Phase 1b: col sums CS[c*56+x] (thread per column) ----
    for (int t = tid; t < CGC * WW; t += NT) {
        int c = t / WW, xp = t - c * WW;
        int base = c * HWP + xp;
        float s = 0.f;
#pragma unroll 8
        for (int y = 0; y < HH; y++) s += SX[base + y * WW];
        CS[t] = s;
    }
    __syncthreads();

    // ---- Phase 2: conv1x1 channel mix + sigmoid -> XH, XW ----
    {
        const float inv56 = 1.f / 56.f;
        for (int idx = tid; idx < CGC * (HH + WW); idx += NT) {
            int o = idx / (HH + WW);
            int l = idx - o * (HH + WW);
            float s = 0.f;
#pragma unroll
            for (int c = 0; c < CGC; c++) {
                float pv = (l < HH) ? RS[c * HH + l] : CS[c * WW + (l - HH)];
                s += W1s[o * CGC + c] * pv;
            }
            float sg = sigm(B1s[o] + s * inv56);
            if (l < HH) XH[o * HH + l] = sg;
            else        XW[o * WW + (l - HH)] = sg;
        }
    }
    __syncthreads();

    // ---- Phase 3: per-channel total sum + stats of t = gx*xh*xw (warp per channel) ----
    {
        int c = warp;  // 16 warps == 16 channels
        float v = RS[c * HH + lane] + ((lane < 24) ? RS[c * HH + 32 + lane] : 0.f);
        v = wred(v);
        if (lane == 0) TT[c] = v;

        float sum = 0.f, sq = 0.f;
        float xwA = XW[c * WW + lane];
        float xwB = (lane < 24) ? XW[c * WW + lane + 32] : 0.f;
#pragma unroll 4
        for (int h = 0; h < HH; h++) {
            float hx = XH[c * HH + h];
            int base = c * HWP + h * WW;
            float t1 = SX[base + lane] * hx * xwA;
            sum += t1; sq += t1 * t1;
            if (lane < 24) {
                float t2 = SX[base + lane + 32] * hx * xwB;
                sum += t2; sq += t2 * t2;
            }
        }
        sum = wred(sum); sq = wred(sq);
        if (lane == 0) {
            const float invhw = 1.f / (float)HWP;
            float mu = sum * invhw;
            float var = sq * invhw - mu * mu;
            if (var < 0.f) var = 0.f;
            float inv = rsqrtf(var + EPSV);
            MU[c] = mu;
            SSv[c] = inv * GNWs[c];
        }
    }
    __syncthreads();

    // ---- Phase 3b step1: shifted sums SA[i*9+k]; a1 = softmax(gn_b); constA ----
    if (tid < 144) {
        int i = tid / 9, k = tid - i * 9;
        int oy = k / 3 - 1, ox = k % 3 - 1;
        float S = TT[i];
        if (oy) S -= RS[i * HH + (oy < 0 ? HH - 1 : 0)];
        if (ox) S -= CS[i * WW + (ox < 0 ? WW - 1 : 0)];
        if (oy && ox) S += SX[i * HWP + (oy < 0 ? HH - 1 : 0) * WW + (ox < 0 ? WW - 1 : 0)];
        SA[tid] = S;
    }
    if (tid == 150) {
        // a1 = softmax(gn_b) (exact: post-GN per-channel mean == gn_b)
        float mx = GNBs[0];
        for (int c = 1; c < CGC; c++) mx = fmaxf(mx, GNBs[c]);
        float ssum = 0.f;
        float e[CGC];
        for (int c = 0; c < CGC; c++) { e[c] = expf(GNBs[c] - mx); ssum += e[c]; }
        float cA = 0.f;
        for (int c = 0; c < CGC; c++) {
            float a = e[c] / ssum;
            A1v[c] = a;
            cA += a * B3s[c];
        }
        CONSTS[0] = cA;
    }
    __syncthreads();

    // ---- Phase 3b step2: collapsed conv weights + x2 channel means ----
    if (tid < 144) {
        float s = 0.f;
#pragma unroll
        for (int o = 0; o < CGC; o++) s += A1v[o] * W3s[o * 144 + tid];
        WC[tid] = s;
    }
    if (tid >= 256 && tid < 256 + CGC) {
        int o = tid - 256;
        float m = 0.f;
#pragma unroll 8
        for (int j = 0; j < 144; j++) m += W3s[o * 144 + j] * SA[j];
        M2[o] = B3s[o] + m * (1.f / (float)HWP);
    }
    __syncthreads();

    // ---- Phase 3b step3: a2 softmax, per-channel coefs, const2 ----
    if (tid == 0) {
        float mx = M2[0];
        for (int c = 1; c < CGC; c++) mx = fmaxf(mx, M2[c]);
        float ssum = 0.f;
        float e[CGC];
        for (int c = 0; c < CGC; c++) { e[c] = expf(M2[c] - mx); ssum += e[c]; }
        float c2 = 0.f;
        for (int c = 0; c < CGC; c++) {
            float a = e[c] / ssum;
            float s = SSv[c];
            A2C[c] = a * s;
            c2 += a * (GNBs[c] - MU[c] * s);
        }
        CONSTS[1] = c2;
    }
    __syncthreads();

    // ---- Phase 5: fused weight map (1-ch conv + coef sum) -> sigmoid -> output ----
    const float wconst = CONSTS[0] + CONSTS[1];
    for (int q = tid; q < (HWP / 4); q += NT) {
        int y = q / (WW / 4);
        int xq = (q - y * (WW / 4)) * 4;
        float4 acc = make_float4(wconst, wconst, wconst, wconst);
#pragma unroll
        for (int c = 0; c < CGC; c++) {
            int rb0 = c * HWP + y * WW;
            float4 v1 = *(const float4*)&SX[rb0 + xq];
            float hx = XH[c * HH + y];
            float4 wv = *(const float4*)&XW[c * WW + xq];
            float cf = A2C[c] * hx;
            acc.x += cf * wv.x * v1.x;
            acc.y += cf * wv.y * v1.y;
            acc.z += cf * wv.z * v1.z;
            acc.w += cf * wv.w * v1.w;
            const float* wcc = &WC[c * 9];
#pragma unroll
            for (int dy = -1; dy <= 1; dy++) {
                int yy = y + dy;
                if (yy < 0 || yy >= HH) continue;
                const float* row = &SX[c * HWP + yy * WW];
                float4 m = (dy == 0) ? v1 : *(const float4*)&row[xq];
                float vm = (xq > 0) ? row[xq - 1] : 0.f;
                float vp = (xq + 4 < WW) ? row[xq + 4] : 0.f;
                float t0 = wcc[(dy + 1) * 3 + 0];
                float t1 = wcc[(dy + 1) * 3 + 1];
                float t2 = wcc[(dy + 1) * 3 + 2];
                acc.x += t0 * vm  + t1 * m.x + t2 * m.y;
                acc.y += t0 * m.x + t1 * m.y + t2 * m.z;
                acc.z += t0 * m.y + t1 * m.z + t2 * m.w;
                acc.w += t0 * m.z + t1 * m.w + t2 * vp;
            }
        }
        float4 sg;
        sg.x = sigm(acc.x); sg.y = sigm(acc.y);
        sg.z = sigm(acc.z); sg.w = sigm(acc.w);
        int pb = y * WW + xq;
#pragma unroll
        for (int c = 0; c < CGC; c++) {
            float4 v = *(const float4*)&SX[c * HWP + pb];
            float4 o4;
            o4.x = v.x * sg.x; o4.y = v.y * sg.y;
            o4.z = v.z * sg.z; o4.w = v.w * sg.w;
            *(float4*)&og[c * HWP + pb] = o4;
        }
    }
}

extern "C" void kernel_launch(void* const* d_in, const int* in_sizes, int n_in,
                              void* d_out, int out_size) {
    const float* x   = (const float*)d_in[0];
    const float* w1  = (const float*)d_in[1];
    const float* b1  = (const float*)d_in[2];
    const float* w3  = (const float*)d_in[3];
    const float* b3  = (const float*)d_in[4];
    const float* gnw = (const float*)d_in[5];
    const float* gnb = (const float*)d_in[6];
    float* out = (float*)d_out;

    cudaFuncSetAttribute(ema_fused_kernel,
                         cudaFuncAttributeMaxDynamicSharedMemorySize, SMEM_BYTES);
    ema_fused_kernel<<<NGRP, NT, SMEM_BYTES>>>(x, w1, b1, w3, b3, gnw, gnb, out);
}

// round 3
// speedup vs baseline: 1.3529x; 1.3529x over previous
#include <cuda_runtime.h>
#include <cstdint>

#define HH 56
#define WW 56
#define HWP 3136
#define CGC 16
#define NGRP 1024
#define NT 512
#define EPSV 1e-5f

// smem float offsets (all float4-aligned)
#define OFF_SX    0
#define OFF_XH    50176
#define OFF_XW    51072
#define OFF_RS    51968
#define OFF_CS    52864
#define OFF_W1    53760
#define OFF_W3    54016
#define OFF_WC    56320   // padded 16*12
#define OFF_SA    56512
#define OFF_B1    56656
#define OFF_B3    56672
#define OFF_GNW   56688
#define OFF_GNB   56704
#define OFF_MU    56720
#define OFF_SS    56736
#define OFF_TT    56752
#define OFF_M2    56768
#define OFF_A1    56784
#define OFF_A2C   56800
#define OFF_CONST 56816
#define SMEM_FLOATS 56824
#define SMEM_BYTES (SMEM_FLOATS * 4)

__device__ __forceinline__ float wred(float v) {
#pragma unroll
    for (int o = 16; o; o >>= 1) v += __shfl_down_sync(0xffffffffu, v, o);
    return v;
}
__device__ __forceinline__ float sigm(float z) { return 1.f / (1.f + __expf(-z)); }

__device__ __forceinline__ void cpa16(unsigned int s, const void* g) {
    asm volatile("cp.async.cg.shared.global [%0], [%1], 16;" :: "r"(s), "l"(g));
}

__global__ __launch_bounds__(NT, 1)
void ema_fused_kernel(const float* __restrict__ x,
                      const float* __restrict__ w1, const float* __restrict__ b1,
                      const float* __restrict__ w3, const float* __restrict__ b3,
                      const float* __restrict__ gnw, const float* __restrict__ gnb,
                      float* __restrict__ out) {
    extern __shared__ float sm[];
    float* SX  = sm + OFF_SX;
    float* XH  = sm + OFF_XH;
    float* XW  = sm + OFF_XW;
    float* RS  = sm + OFF_RS;
    float* CS  = sm + OFF_CS;
    float* W1s = sm + OFF_W1;
    float* W3s = sm + OFF_W3;
    float* WCp = sm + OFF_WC;
    float* SA  = sm + OFF_SA;
    float* B1s = sm + OFF_B1;
    float* B3s = sm + OFF_B3;
    float* GNWs = sm + OFF_GNW;
    float* GNBs = sm + OFF_GNB;
    float* MU  = sm + OFF_MU;
    float* SSv = sm + OFF_SS;
    float* TT  = sm + OFF_TT;
    float* M2  = sm + OFF_M2;
    float* A1v = sm + OFF_A1;
    float* A2C = sm + OFF_A2C;
    float* CONSTS = sm + OFF_CONST;

    const int tid = threadIdx.x;
    const int g = blockIdx.x;
    const float* gx = x + (size_t)g * (CGC * HWP);
    float* og = out + (size_t)g * (CGC * HWP);

    // ---- Phase 0: async-load tile + params into SMEM ----
    {
        unsigned int smb = (unsigned int)__cvta_generic_to_shared(sm);
        const float4* gx4 = (const float4*)gx;
        unsigned int sx_s = smb + OFF_SX * 4;
#pragma unroll 4
        for (int i = tid; i < (CGC * HWP) / 4; i += NT)
            cpa16(sx_s + i * 16, gx4 + i);
        const float4* w34 = (const float4*)w3;
        unsigned int w3_s = smb + OFF_W3 * 4;
        for (int i = tid; i < 2304 / 4; i += NT)
            cpa16(w3_s + i * 16, w34 + i);
        if (tid < 64) cpa16(smb + OFF_W1 * 4 + tid * 16, (const float4*)w1 + tid);
        if (tid < 4) {
            cpa16(smb + OFF_B1 * 4 + tid * 16, (const float4*)b1 + tid);
            cpa16(smb + OFF_B3 * 4 + tid * 16, (const float4*)b3 + tid);
            cpa16(smb + OFF_GNW * 4 + tid * 16, (const float4*)gnw + tid);
            cpa16(smb + OFF_GNB * 4 + tid * 16, (const float4*)gnb + tid);
        }
        asm volatile("cp.async.commit_group;" ::: "memory");
        asm volatile("cp.async.wait_group 0;" ::: "memory");
    }
    __syncthreads();

    const int warp = tid >> 5;
    const int lane = tid & 31;

    // ---- Phase 1a: row sums RS[c*56+h] (thread per row, float4 serial) ----
    for (int r = tid; r < CGC * HH; r += NT) {
        const float4* row = (const float4*)&SX[r * WW];
        float s0 = 0.f, s1 = 0.f, s2 = 0.f, s3 = 0.f;
#pragma unroll
        for (int j = 0; j < 14; j += 2) {
            float4 a = row[j], b = row[j + 1];
            s0 += a.x + a.y; s1 += a.z + a.w;
            s2 += b.x + b.y; s3 += b.z + b.w;
        }
        RS[r] = (s0 + s1) + (s2 + s3);
    }
    // ---- Phase 1b: col sums CS[c*56+x] (thread per column) ----
    for (int t = tid; t < CGC * WW; t += NT) {
        int c = t / WW, xp = t - c * WW;
        const float* base = &SX[c * HWP + xp];
        float sA = 0.f, sB = 0.f;
#pragma unroll 8
        for (int y = 0; y < HH; y += 2) { sA += base[y * WW]; sB += base[(y + 1) * WW]; }
        CS[t] = sA + sB;
    }
    __syncthreads();

    // ---- Phase 2: conv1x1 channel mix + sigmoid -> XH, XW ----
    {
        const float inv56 = 1.f / 56.f;
        for (int idx = tid; idx < CGC * (HH + WW); idx += NT) {
            int o = idx / (HH + WW);
            int l = idx - o * (HH + WW);
            float s = 0.f;
#pragma unroll
            for (int c = 0; c < CGC; c++) {
                float pv = (l < HH) ? RS[c * HH + l] : CS[c * WW + (l - HH)];
                s += W1s[o * CGC + c] * pv;
            }
            float sg = sigm(B1s[o] + s * inv56);
            if (l < HH) XH[o * HH + l] = sg;
            else        XW[o * WW + (l - HH)] = sg;
        }
    }
    __syncthreads();

    // ---- Phase 3: per-channel total sum + stats of t = gx*xh*xw (warp per channel) ----
    {
        int c = warp;
        float v = RS[c * HH + lane] + ((lane < 24) ? RS[c * HH + 32 + lane] : 0.f);
        v = wred(v);
        if (lane == 0) TT[c] = v;

        float sum = 0.f, sq = 0.f;
        float xwA = XW[c * WW + lane];
        float xwB = (lane < 24) ? XW[c * WW + lane + 32] : 0.f;
#pragma unroll 4
        for (int h = 0; h < HH; h++) {
            float hx = XH[c * HH + h];
            const float* base = &SX[c * HWP + h * WW];
            float t1 = base[lane] * hx * xwA;
            sum += t1; sq += t1 * t1;
            if (lane < 24) {
                float t2 = base[lane + 32] * hx * xwB;
                sum += t2; sq += t2 * t2;
            }
        }
        sum = wred(sum); sq = wred(sq);
        if (lane == 0) {
            const float invhw = 1.f / (float)HWP;
            float mu = sum * invhw;
            float var = sq * invhw - mu * mu;
            if (var < 0.f) var = 0.f;
            float inv = rsqrtf(var + EPSV);
            MU[c] = mu;
            SSv[c] = inv * GNWs[c];
        }
    }
    __syncthreads();

    // ---- Phase 3b step1: shifted sums SA; a1 = softmax(gn_b); constA ----
    if (tid < 144) {
        int i = tid / 9, k = tid - i * 9;
        int oy = k / 3 - 1, ox = k % 3 - 1;
        float S = TT[i];
        if (oy) S -= RS[i * HH + (oy < 0 ? HH - 1 : 0)];
        if (ox) S -= CS[i * WW + (ox < 0 ? WW - 1 : 0)];
        if (oy && ox) S += SX[i * HWP + (oy < 0 ? HH - 1 : 0) * WW + (ox < 0 ? WW - 1 : 0)];
        SA[tid] = S;
    }
    if (tid == 150) {
        float mx = GNBs[0];
        for (int c = 1; c < CGC; c++) mx = fmaxf(mx, GNBs[c]);
        float ssum = 0.f;
        float e[CGC];
        for (int c = 0; c < CGC; c++) { e[c] = expf(GNBs[c] - mx); ssum += e[c]; }
        float cA = 0.f;
        for (int c = 0; c < CGC; c++) {
            float a = e[c] / ssum;
            A1v[c] = a;
            cA += a * B3s[c];
        }
        CONSTS[0] = cA;
    }
    __syncthreads();

    // ---- Phase 3b step2: collapsed conv weights (12-padded) + x2 channel means ----
    if (tid < 144) {
        int i = tid / 9, k = tid - i * 9;
        float s = 0.f;
#pragma unroll
        for (int o = 0; o < CGC; o++) s += A1v[o] * W3s[o * 144 + tid];
        WCp[i * 12 + k] = s;
    }
    if (tid >= 256 && tid < 256 + CGC) {
        int o = tid - 256;
        float m = 0.f;
#pragma unroll 8
        for (int j = 0; j < 144; j++) m += W3s[o * 144 + j] * SA[j];
        M2[o] = B3s[o] + m * (1.f / (float)HWP);
    }
    __syncthreads();

    // ---- Phase 3b step3: a2 softmax, per-channel coefs, const2 ----
    if (tid == 0) {
        float mx = M2[0];
        for (int c = 1; c < CGC; c++) mx = fmaxf(mx, M2[c]);
        float ssum = 0.f;
        float e[CGC];
        for (int c = 0; c < CGC; c++) { e[c] = expf(M2[c] - mx); ssum += e[c]; }
        float c2 = 0.f;
        for (int c = 0; c < CGC; c++) {
            float a = e[c] / ssum;
            float s = SSv[c];
            A2C[c] = a * s;
            c2 += a * (GNBs[c] - MU[c] * s);
        }
        CONSTS[1] = c2;
    }
    __syncthreads();

    // ---- Phase 5: fused weight map -> sigmoid -> output (aligned float4 windows) ----
    const float wconst = CONSTS[0] + CONSTS[1];
    const float4 zero4 = make_float4(0.f, 0.f, 0.f, 0.f);
    for (int q = tid; q < (HWP / 4); q += NT) {
        int y = q / (WW / 4);
        int xq4 = q - y * (WW / 4);
        int xq = xq4 * 4;
        float mt = (y > 0) ? 1.f : 0.f;
        float mb = (y < HH - 1) ? 1.f : 0.f;
        int yt = (y > 0) ? y - 1 : 0;
        int yb = (y < HH - 1) ? y + 1 : y;
        float a0 = wconst, a1a = wconst, a2a = wconst, a3 = wconst;
#pragma unroll
        for (int c = 0; c < CGC; c++) {
            const float* cw = &WCp[c * 12];
            float4 wA = *(const float4*)cw;
            float4 wB = *(const float4*)(cw + 4);
            float w8 = cw[8];
            float hx = XH[c * HH + y];
            float4 wv = *(const float4*)&XW[c * WW + xq];
            float cf = A2C[c] * hx;
            const float4* b4 = (const float4*)&SX[c * HWP];
            // top row
            {
                const float4* r4 = b4 + yt * (WW / 4);
                float4 Av = (xq4 > 0) ? r4[xq4 - 1] : zero4;
                float4 Bv = r4[xq4];
                float4 Cv = (xq4 < 13) ? r4[xq4 + 1] : zero4;
                float t0 = wA.x * mt, t1 = wA.y * mt, t2 = wA.z * mt;
                a0  += t0 * Av.w + t1 * Bv.x + t2 * Bv.y;
                a1a += t0 * Bv.x + t1 * Bv.y + t2 * Bv.z;
                a2a += t0 * Bv.y + t1 * Bv.z + t2 * Bv.w;
                a3  += t0 * Bv.z + t1 * Bv.w + t2 * Cv.x;
            }
            // mid row (+ cf part)
            {
                const float4* r4 = b4 + y * (WW / 4);
                float4 Av = (xq4 > 0) ? r4[xq4 - 1] : zero4;
                float4 Bv = r4[xq4];
                float4 Cv = (xq4 < 13) ? r4[xq4 + 1] : zero4;
                float t0 = wA.w, t1 = wB.x, t2 = wB.y;
                a0  += t0 * Av.w + t1 * Bv.x + t2 * Bv.y;
                a1a += t0 * Bv.x + t1 * Bv.y + t2 * Bv.z;
                a2a += t0 * Bv.y + t1 * Bv.z + t2 * Bv.w;
                a3  += t0 * Bv.z + t1 * Bv.w + t2 * Cv.x;
                a0  += cf * wv.x * Bv.x;
                a1a += cf * wv.y * Bv.y;
                a2a += cf * wv.z * Bv.z;
                a3  += cf * wv.w * Bv.w;
            }
            // bottom row
            {
                const float4* r4 = b4 + yb * (WW / 4);
                float4 Av = (xq4 > 0) ? r4[xq4 - 1] : zero4;
                float4 Bv = r4[xq4];
                float4 Cv = (xq4 < 13) ? r4[xq4 + 1] : zero4;
                float t0 = wB.z * mb, t1 = wB.w * mb, t2 = w8 * mb;
                a0  += t0 * Av.w + t1 * Bv.x + t2 * Bv.y;
                a1a += t0 * Bv.x + t1 * Bv.y + t2 * Bv.z;
                a2a += t0 * Bv.y + t1 * Bv.z + t2 * Bv.w;
                a3  += t0 * Bv.z + t1 * Bv.w + t2 * Cv.x;
            }
        }
        float s0 = sigm(a0), s1 = sigm(a1a), s2 = sigm(a2a), s3 = sigm(a3);
        int pb = y * WW + xq;
#pragma unroll
        for (int c = 0; c < CGC; c++) {
            float4 v = *(const float4*)&SX[c * HWP + pb];
            float4 o4;
            o4.x = v.x * s0; o4.y = v.y * s1;
            o4.z = v.z * s2; o4.w = v.w * s3;
            *(float4*)&og[c * HWP + pb] = o4;
        }
    }
}

extern "C" void kernel_launch(void* const* d_in, const int* in_sizes, int n_in,
                              void* d_out, int out_size) {
    const float* x   = (const float*)d_in[0];
    const float* w1  = (const float*)d_in[1];
    const float* b1  = (const float*)d_in[2];
    const float* w3  = (const float*)d_in[3];
    const float* b3  = (const float*)d_in[4];
    const float* gnw = (const float*)d_in[5];
    const float* gnb = (const float*)d_in[6];
    float* out = (float*)d_out;

    cudaFuncSetAttribute(ema_fused_kernel,
                         cudaFuncAttributeMaxDynamicSharedMemorySize, SMEM_BYTES);
    ema_fused_kernel<<<NGRP, NT, SMEM_BYTES>>>(x, w1, b1, w3, b3, gnw, gnb, out);
}

// round 5
// speedup vs baseline: 1.7359x; 1.2831x over previous
#include <cuda_runtime.h>
#include <cstdint>

#define HH 56
#define WW 56
#define HWP 3136
#define CGC 16
#define NGRP 1024
#define NT 512
#define EPSV 1e-5f

#define OFF_SX    0
#define OFF_XH    50176
#define OFF_XW    51072
#define OFF_RS    51968
#define OFF_CS    52864
#define OFF_W1    53760
#define OFF_W3    54016
#define OFF_WC    56320
#define OFF_SA    56512
#define OFF_B1    56656
#define OFF_B3    56672
#define OFF_GNW   56688
#define OFF_GNB   56704
#define OFF_MU    56720
#define OFF_SS    56736
#define OFF_TT    56752
#define OFF_M2    56768
#define OFF_A1    56784
#define OFF_A2C   56800
#define OFF_CONST 56816
#define SMEM_FLOATS 56824
#define SMEM_BYTES (SMEM_FLOATS * 4)
// PM (partial weight map, 3136 floats) overlays RS..W3 (dead before phase 5)
#define OFF_PM    OFF_RS

__device__ __forceinline__ float wred(float v) {
#pragma unroll
    for (int o = 16; o; o >>= 1) v += __shfl_down_sync(0xffffffffu, v, o);
    return v;
}
__device__ __forceinline__ float sigm(float z) { return 1.f / (1.f + __expf(-z)); }

__device__ __forceinline__ void cpa16(unsigned int s, const void* g) {
    asm volatile("cp.async.cg.shared.global [%0], [%1], 16;" :: "r"(s), "l"(g));
}

#define TAPS(acc, t0, t1, t2, avw, Bv, cvx) do { \
    acc.x += t0 * (avw) + t1 * Bv.x + t2 * Bv.y; \
    acc.y += t0 * Bv.x  + t1 * Bv.y + t2 * Bv.z; \
    acc.z += t0 * Bv.y  + t1 * Bv.z + t2 * Bv.w; \
    acc.w += t0 * Bv.z  + t1 * Bv.w + t2 * (cvx); } while (0)

__global__ __launch_bounds__(NT, 1)
void ema_fused_kernel(const float* __restrict__ x,
                      const float* __restrict__ w1, const float* __restrict__ b1,
                      const float* __restrict__ w3, const float* __restrict__ b3,
                      const float* __restrict__ gnw, const float* __restrict__ gnb,
                      float* __restrict__ out) {
    extern __shared__ float sm[];
    float* SX  = sm + OFF_SX;
    float* XH  = sm + OFF_XH;
    float* XW  = sm + OFF_XW;
    float* RS  = sm + OFF_RS;
    float* CS  = sm + OFF_CS;
    float* W1s = sm + OFF_W1;
    float* W3s = sm + OFF_W3;
    float* WCp = sm + OFF_WC;
    float* SA  = sm + OFF_SA;
    float* B1s = sm + OFF_B1;
    float* B3s = sm + OFF_B3;
    float* GNWs = sm + OFF_GNW;
    float* GNBs = sm + OFF_GNB;
    float* MU  = sm + OFF_MU;
    float* SSv = sm + OFF_SS;
    float* TT  = sm + OFF_TT;
    float* M2  = sm + OFF_M2;
    float* A1v = sm + OFF_A1;
    float* A2C = sm + OFF_A2C;
    float* CONSTS = sm + OFF_CONST;
    float* PM  = sm + OFF_PM;

    const int tid = threadIdx.x;
    const int g = blockIdx.x;
    const float* gx = x + (size_t)g * (CGC * HWP);
    float* og = out + (size_t)g * (CGC * HWP);

    // ---- Phase 0: async-load tile + params ----
    {
        unsigned int smb = (unsigned int)__cvta_generic_to_shared(sm);
        const float4* gx4 = (const float4*)gx;
        unsigned int sx_s = smb + OFF_SX * 4;
#pragma unroll 4
        for (int i = tid; i < (CGC * HWP) / 4; i += NT)
            cpa16(sx_s + i * 16, gx4 + i);
        const float4* w34 = (const float4*)w3;
        unsigned int w3_s = smb + OFF_W3 * 4;
        for (int i = tid; i < 2304 / 4; i += NT)
            cpa16(w3_s + i * 16, w34 + i);
        if (tid < 64) cpa16(smb + OFF_W1 * 4 + tid * 16, (const float4*)w1 + tid);
        if (tid < 4) {
            cpa16(smb + OFF_B1 * 4 + tid * 16, (const float4*)b1 + tid);
            cpa16(smb + OFF_B3 * 4 + tid * 16, (const float4*)b3 + tid);
            cpa16(smb + OFF_GNW * 4 + tid * 16, (const float4*)gnw + tid);
            cpa16(smb + OFF_GNB * 4 + tid * 16, (const float4*)gnb + tid);
        }
        asm volatile("cp.async.commit_group;" ::: "memory");
        asm volatile("cp.async.wait_group 0;" ::: "memory");
    }
    __syncthreads();

    const int warp = tid >> 5;
    const int lane = tid & 31;

    // ---- Phase 1a: row sums (thread per row, float4) ----
    for (int r = tid; r < CGC * HH; r += NT) {
        const float4* row = (const float4*)&SX[r * WW];
        float s0 = 0.f, s1 = 0.f, s2 = 0.f, s3 = 0.f;
#pragma unroll
        for (int j = 0; j < 14; j += 2) {
            float4 a = row[j], b = row[j + 1];
            s0 += a.x + a.y; s1 += a.z + a.w;
            s2 += b.x + b.y; s3 += b.z + b.w;
        }
        RS[r] = (s0 + s1) + (s2 + s3);
    }
    // ---- Phase 1b: col sums ----
    for (int t = tid; t < CGC * WW; t += NT) {
        int c = t / WW, xp = t - c * WW;
        const float* base = &SX[c * HWP + xp];
        float sA = 0.f, sB = 0.f;
#pragma unroll 8
        for (int y = 0; y < HH; y += 2) { sA += base[y * WW]; sB += base[(y + 1) * WW]; }
        CS[t] = sA + sB;
    }
    __syncthreads();

    // ---- Phase 2: conv1x1 + sigmoid -> XH, XW ----
    {
        const float inv56 = 1.f / 56.f;
        for (int idx = tid; idx < CGC * (HH + WW); idx += NT) {
            int o = idx / (HH + WW);
            int l = idx - o * (HH + WW);
            float s = 0.f;
#pragma unroll
            for (int c = 0; c < CGC; c++) {
                float pv = (l < HH) ? RS[c * HH + l] : CS[c * WW + (l - HH)];
                s += W1s[o * CGC + c] * pv;
            }
            float sg = sigm(B1s[o] + s * inv56);
            if (l < HH) XH[o * HH + l] = sg;
            else        XW[o * WW + (l - HH)] = sg;
        }
    }
    __syncthreads();

    // ---- Phase 3: per-channel total + stats of t = gx*xh*xw (warp per channel, float4) ----
    {
        int c = warp;
        float v = RS[c * HH + lane] + ((lane < 24) ? RS[c * HH + 32 + lane] : 0.f);
        v = wred(v);
        if (lane == 0) TT[c] = v;

        int sub = lane >> 4;
        int l16 = lane & 15;
        bool act = (l16 < 14);
        int xqe = act ? l16 : 13;
        float4 xw4 = ((const float4*)&XW[c * WW])[xqe];
        float4 s4 = make_float4(0.f, 0.f, 0.f, 0.f);
        float4 q4 = make_float4(0.f, 0.f, 0.f, 0.f);
        const float4* ch4 = (const float4*)&SX[c * HWP];
#pragma unroll 4
        for (int hh = 0; hh < 28; hh++) {
            int y = hh * 2 + sub;
            float hx = XH[c * HH + y];
            float4 vv = ch4[y * 14 + xqe];
            if (act) {
                float t0 = vv.x * hx * xw4.x, t1 = vv.y * hx * xw4.y;
                float t2 = vv.z * hx * xw4.z, t3 = vv.w * hx * xw4.w;
                s4.x += t0; s4.y += t1; s4.z += t2; s4.w += t3;
                q4.x += t0 * t0; q4.y += t1 * t1; q4.z += t2 * t2; q4.w += t3 * t3;
            }
        }
        float sum = (s4.x + s4.y) + (s4.z + s4.w);
        float sq  = (q4.x + q4.y) + (q4.z + q4.w);
        sum = wred(sum); sq = wred(sq);
        if (lane == 0) {
            const float invhw = 1.f / (float)HWP;
            float mu = sum * invhw;
            float var = sq * invhw - mu * mu;
            if (var < 0.f) var = 0.f;
            float inv = rsqrtf(var + EPSV);
            MU[c] = mu;
            SSv[c] = inv * GNWs[c];
        }
    }
    __syncthreads();

    // ---- Phase 3b step1: shifted sums SA; a1 = softmax(gn_b); constA ----
    if (tid < 144) {
        int i = tid / 9, k = tid - i * 9;
        int oy = k / 3 - 1, ox = k % 3 - 1;
        float S = TT[i];
        if (oy) S -= RS[i * HH + (oy < 0 ? HH - 1 : 0)];
        if (ox) S -= CS[i * WW + (ox < 0 ? WW - 1 : 0)];
        if (oy && ox) S += SX[i * HWP + (oy < 0 ? HH - 1 : 0) * WW + (ox < 0 ? WW - 1 : 0)];
        SA[tid] = S;
    }
    if (tid == 150) {
        float mx = GNBs[0];
        for (int c = 1; c < CGC; c++) mx = fmaxf(mx, GNBs[c]);
        float ssum = 0.f;
        float e[CGC];
        for (int c = 0; c < CGC; c++) { e[c] = expf(GNBs[c] - mx); ssum += e[c]; }
        float cA = 0.f;
        for (int c = 0; c < CGC; c++) {
            float a = e[c] / ssum;
            A1v[c] = a;
            cA += a * B3s[c];
        }
        CONSTS[0] = cA;
    }
    __syncthreads();

    // ---- Phase 3b step2: collapsed conv weights (12-padded) + x2 channel means ----
    if (tid < 144) {
        int i = tid / 9, k = tid - i * 9;
        float s = 0.f;
#pragma unroll
        for (int o = 0; o < CGC; o++) s += A1v[o] * W3s[o * 144 + tid];
        WCp[i * 12 + k] = s;
    }
    if (tid >= 256 && tid < 256 + CGC) {
        int o = tid - 256;
        float m = 0.f;
#pragma unroll 8
        for (int j = 0; j < 144; j++) m += W3s[o * 144 + j] * SA[j];
        M2[o] = B3s[o] + m * (1.f / (float)HWP);
    }
    __syncthreads();

    // ---- Phase 3b step3: a2 softmax, per-channel coefs, const2 ----
    if (tid == 0) {
        float mx = M2[0];
        for (int c = 1; c < CGC; c++) mx = fmaxf(mx, M2[c]);
        float ssum = 0.f;
        float e[CGC];
        for (int c = 0; c < CGC; c++) { e[c] = expf(M2[c] - mx); ssum += e[c]; }
        float c2 = 0.f;
        for (int c = 0; c < CGC; c++) {
            float a = e[c] / ssum;
            float s = SSv[c];
            A2C[c] = a * s;
            c2 += a * (GNBs[c] - MU[c] * s);
        }
        CONSTS[1] = c2;
    }
    __syncthreads();
    // ==== RS/CS/W1/W3 are dead from here; PM overlays them ====

    // ---- Phase 5a: partial weight map. 896 slots: [h(2)][rowpair(28)][lane16(16)] ----
    // All shuffles unconditional; row-edge handling via clamped row index + zeroed tap weights.
    float4 aA[2], aB[2];
    int uh[2], uy0[2], ul[2];
    bool uact[2];
#pragma unroll
    for (int it = 0; it < 2; it++) {
        uact[it] = false;
        int s = tid + it * NT;
        bool slot = (s < 896);               // warp-uniform (896 = 28 warps)
        int sc = slot ? s : 0;
        int h = sc / 448;
        int t = sc - h * 448;
        int rr = t >> 4;
        int l16 = t & 15;
        int y0 = rr * 2;
        bool act = slot && (l16 < 14);
        int xqe = (l16 < 14) ? l16 : 13;
        uh[it] = h; uy0[it] = y0; ul[it] = l16; uact[it] = act;
        float mt = (y0 > 0) ? 1.f : 0.f;     // top edge mask
        float mb = (y0 < 54) ? 1.f : 0.f;    // bottom edge mask
        int ytop = (y0 > 0) ? y0 - 1 : 0;
        int ybot = (y0 < 54) ? y0 + 2 : 55;
        float4 A = make_float4(0.f, 0.f, 0.f, 0.f);
        float4 B = make_float4(0.f, 0.f, 0.f, 0.f);
        const int cbase = h * 8;
#pragma unroll
        for (int ci = 0; ci < 8; ci++) {
            int c = cbase + ci;
            const float* cw = &WCp[c * 12];
            float4 wA = *(const float4*)cw;
            float4 wB = *(const float4*)(cw + 4);
            float w8 = cw[8];
            float4 wv = ((const float4*)&XW[c * WW])[xqe];
            float a2c = A2C[c];
            float cf0 = a2c * XH[c * HH + y0];
            float cf1 = a2c * XH[c * HH + y0 + 1];
            const float4* ch4 = (const float4*)&SX[c * HWP];
            {  // row ytop (masked by mt) -> top of out0
                float4 Bv = ch4[ytop * 14 + xqe];
                float avw = __shfl_up_sync(0xffffffffu, Bv.w, 1, 16);
                float cvx = __shfl_down_sync(0xffffffffu, Bv.x, 1, 16);
                if (l16 == 0) avw = 0.f;
                if (l16 == 13) cvx = 0.f;
                TAPS(A, wA.x * mt, wA.y * mt, wA.z * mt, avw, Bv, cvx);
            }
            {  // row y0 -> mid of out0, top of out1, cf0 term
                float4 Bv = ch4[y0 * 14 + xqe];
                float avw = __shfl_up_sync(0xffffffffu, Bv.w, 1, 16);
                float cvx = __shfl_down_sync(0xffffffffu, Bv.x, 1, 16);
                if (l16 == 0) avw = 0.f;
                if (l16 == 13) cvx = 0.f;
                TAPS(A, wA.w, wB.x, wB.y, avw, Bv, cvx);
                TAPS(B, wA.x, wA.y, wA.z, avw, Bv, cvx);
                A.x += cf0 * wv.x * Bv.x;
                A.y += cf0 * wv.y * Bv.y;
                A.z += cf0 * wv.z * Bv.z;
                A.w += cf0 * wv.w * Bv.w;
            }
            {  // row y0+1 -> bottom of out0, mid of out1, cf1 term
                float4 Bv = ch4[(y0 + 1) * 14 + xqe];
                float avw = __shfl_up_sync(0xffffffffu, Bv.w, 1, 16);
                float cvx = __shfl_down_sync(0xffffffffu, Bv.x, 1, 16);
                if (l16 == 0) avw = 0.f;
                if (l16 == 13) cvx = 0.f;
                TAPS(A, wB.z, wB.w, w8, avw, Bv, cvx);
                TAPS(B, wA.w, wB.x, wB.y, avw, Bv, cvx);
                B.x += cf1 * wv.x * Bv.x;
                B.y += cf1 * wv.y * Bv.y;
                B.z += cf1 * wv.z * Bv.z;
                B.w += cf1 * wv.w * Bv.w;
            }
            {  // row ybot (masked by mb) -> bottom of out1
                float4 Bv = ch4[ybot * 14 + xqe];
                float avw = __shfl_up_sync(0xffffffffu, Bv.w, 1, 16);
                float cvx = __shfl_down_sync(0xffffffffu, Bv.x, 1, 16);
                if (l16 == 0) avw = 0.f;
                if (l16 == 13) cvx = 0.f;
                TAPS(B, wB.z * mb, wB.w * mb, w8 * mb, avw, Bv, cvx);
            }
        }
        aA[it] = A; aB[it] = B;
    }
    // h0 writes PM
#pragma unroll
    for (int it = 0; it < 2; it++)
        if (uact[it] && uh[it] == 0) {
            ((float4*)&PM[uy0[it] * WW])[ul[it]] = aA[it];
            ((float4*)&PM[(uy0[it] + 1) * WW])[ul[it]] = aB[it];
        }
    __syncthreads();
    // h1 read-add-write
#pragma unroll
    for (int it = 0; it < 2; it++)
        if (uact[it] && uh[it] == 1) {
            float4* p0 = &((float4*)&PM[uy0[it] * WW])[ul[it]];
            float4* p1 = &((float4*)&PM[(uy0[it] + 1) * WW])[ul[it]];
            float4 v0 = *p0, v1 = *p1;
            v0.x += aA[it].x; v0.y += aA[it].y; v0.z += aA[it].z; v0.w += aA[it].w;
            v1.x += aB[it].x; v1.y += aB[it].y; v1.z += aB[it].z; v1.w += aB[it].w;
            *p0 = v0; *p1 = v1;
        }
    __syncthreads();

    // ---- Phase 5b: sigmoid(weights) * gx -> out ----
    const float wconst = CONSTS[0] + CONSTS[1];
    const float4* PM4 = (const float4*)PM;
    for (int q = tid; q < (HWP / 4); q += NT) {
        float4 p = PM4[q];
        float s0 = sigm(p.x + wconst), s1 = sigm(p.y + wconst);
        float s2 = sigm(p.z + wconst), s3 = sigm(p.w + wconst);
        int pb = q * 4;
#pragma unroll
        for (int c = 0; c < CGC; c++) {
            float4 v = *(const float4*)&SX[c * HWP + pb];
            float4 o4;
            o4.x = v.x * s0; o4.y = v.y * s1;
            o4.z = v.z * s2; o4.w = v.w * s3;
            *(float4*)&og[c * HWP + pb] = o4;
        }
    }
}

extern "C" void kernel_launch(void* const* d_in, const int* in_sizes, int n_in,
                              void* d_out, int out_size) {
    const float* x   = (const float*)d_in[0];
    const float* w1  = (const float*)d_in[1];
    const float* b1  = (const float*)d_in[2];
    const float* w3  = (const float*)d_in[3];
    const float* b3  = (const float*)d_in[4];
    const float* gnw = (const float*)d_in[5];
    const float* gnb = (const float*)d_in[6];
    float* out = (float*)d_out;

    cudaFuncSetAttribute(ema_fused_kernel,
                         cudaFuncAttributeMaxDynamicSharedMemorySize, SMEM_BYTES);
    ema_fused_kernel<<<NGRP, NT, SMEM_BYTES>>>(x, w1, b1, w3, b3, gnw, gnb, out);
}

// round 6
// speedup vs baseline: 1.8740x; 1.0795x over previous
#include <cuda_runtime.h>
#include <cuda_fp16.h>
#include <cstdint>

#define HH 56
#define WW 56
#define HWP 3136
#define CGC 16
#define NGRP 1024
#define NT 256
#define EPSV 1e-5f

// byte offsets into dynamic smem
#define OB_SX    0        // fp16 tile 16*3136
#define OB_XH    100352   // fp16 16*56
#define OB_XW    102144
#define OB_RS    103936
#define OB_CS    105728
#define OB_W1    107520   // fp32 256
#define OB_WC    108544   // fp32 16*12
#define OB_SA    109312   // fp32 144
#define OB_B1    109888
#define OB_B3    109952
#define OB_GNW   110016
#define OB_GNB   110080
#define OB_MU    110144
#define OB_SS    110208
#define OB_TT    110272
#define OB_M2    110336
#define OB_A1    110400
#define OB_A2C   110464
#define OB_CONST 110528
#define SMEM_BYTES 110592

__device__ __forceinline__ float wred(float v) {
#pragma unroll
    for (int o = 16; o; o >>= 1) v += __shfl_down_sync(0xffffffffu, v, o);
    return v;
}
__device__ __forceinline__ float sigm(float z) { return 1.f / (1.f + __expf(-z)); }

__device__ __forceinline__ float4 h4tof4(uint2 u) {
    __half2 a = *reinterpret_cast<__half2*>(&u.x);
    __half2 b = *reinterpret_cast<__half2*>(&u.y);
    float2 fa = __half22float2(a), fb = __half22float2(b);
    return make_float4(fa.x, fa.y, fb.x, fb.y);
}

#define TAPS(acc, t0, t1, t2, avw, Bv, cvx) do { \
    acc.x += (t0) * (avw) + (t1) * Bv.x + (t2) * Bv.y; \
    acc.y += (t0) * Bv.x  + (t1) * Bv.y + (t2) * Bv.z; \
    acc.z += (t0) * Bv.y  + (t1) * Bv.z + (t2) * Bv.w; \
    acc.w += (t0) * Bv.z  + (t1) * Bv.w + (t2) * (cvx); } while (0)

#define GETROW(ry, Bv, avw, cvx) do { \
    Bv = h4tof4(*(const uint2*)(chb + (ry) * WW + xqe * 4)); \
    avw = __shfl_up_sync(0xffffffffu, Bv.w, 1, 16); \
    cvx = __shfl_down_sync(0xffffffffu, Bv.x, 1, 16); \
    if (l16 == 0) avw = 0.f; \
    if (l16 == 13) cvx = 0.f; } while (0)

__global__ __launch_bounds__(NT, 2)
void ema_fused_kernel(const float* __restrict__ x,
                      const float* __restrict__ w1, const float* __restrict__ b1,
                      const float* __restrict__ w3, const float* __restrict__ b3,
                      const float* __restrict__ gnw, const float* __restrict__ gnb,
                      float* __restrict__ out) {
    extern __shared__ char smc[];
    __half* SXH = (__half*)(smc + OB_SX);
    __half* XHh = (__half*)(smc + OB_XH);
    __half* XWh = (__half*)(smc + OB_XW);
    __half* RSh = (__half*)(smc + OB_RS);
    __half* CSh = (__half*)(smc + OB_CS);
    float* W1s = (float*)(smc + OB_W1);
    float* WCp = (float*)(smc + OB_WC);
    float* SA  = (float*)(smc + OB_SA);
    float* B1s = (float*)(smc + OB_B1);
    float* B3s = (float*)(smc + OB_B3);
    float* GNWs = (float*)(smc + OB_GNW);
    float* GNBs = (float*)(smc + OB_GNB);
    float* MU  = (float*)(smc + OB_MU);
    float* SSv = (float*)(smc + OB_SS);
    float* TT  = (float*)(smc + OB_TT);
    float* M2  = (float*)(smc + OB_M2);
    float* A1v = (float*)(smc + OB_A1);
    float* A2C = (float*)(smc + OB_A2C);
    float* CONSTS = (float*)(smc + OB_CONST);

    const int tid = threadIdx.x;
    const int g = blockIdx.x;
    const float* gx = x + (size_t)g * (CGC * HWP);
    float* og = out + (size_t)g * (CGC * HWP);

    const int warp = tid >> 5;
    const int lane = tid & 31;

    // ---- Phase 0: load tile (fp32 -> fp16) + params ----
    {
        const float4* gx4 = (const float4*)gx;
#pragma unroll 4
        for (int i = tid; i < (CGC * HWP) / 4; i += NT) {
            float4 v = gx4[i];
            __half2 h0 = __floats2half2_rn(v.x, v.y);
            __half2 h1 = __floats2half2_rn(v.z, v.w);
            uint2 u;
            u.x = *(unsigned int*)&h0;
            u.y = *(unsigned int*)&h1;
            *(uint2*)(SXH + i * 4) = u;
        }
        if (tid < 256) W1s[tid] = w1[tid];
        if (tid < 16) {
            B1s[tid] = b1[tid]; B3s[tid] = b3[tid];
            GNWs[tid] = gnw[tid]; GNBs[tid] = gnb[tid];
        }
    }
    __syncthreads();

    // ---- Phase 1a: row sums (thread per row, uint4 of 8 halfs) ----
    for (int r = tid; r < CGC * HH; r += NT) {
        const uint4* row = (const uint4*)(SXH + r * WW);
        float s = 0.f;
#pragma unroll
        for (int j = 0; j < 7; j++) {
            uint4 u = row[j];
            float4 a = h4tof4(make_uint2(u.x, u.y));
            float4 b = h4tof4(make_uint2(u.z, u.w));
            s += (a.x + a.y) + (a.z + a.w) + (b.x + b.y) + (b.z + b.w);
        }
        RSh[r] = __float2half_rn(s);
    }
    // ---- Phase 1b: col sums ----
    for (int t = tid; t < CGC * WW; t += NT) {
        int c = t / WW, xp = t - c * WW;
        const __half* base = SXH + c * HWP + xp;
        float sA = 0.f, sB = 0.f;
#pragma unroll 8
        for (int y = 0; y < HH; y += 2) {
            sA += __half2float(base[y * WW]);
            sB += __half2float(base[(y + 1) * WW]);
        }
        CSh[t] = __float2half_rn(sA + sB);
    }
    __syncthreads();

    // ---- Phase 2: conv1x1 channel mix + sigmoid -> XH, XW ----
    {
        const float inv56 = 1.f / 56.f;
        for (int idx = tid; idx < CGC * (HH + WW); idx += NT) {
            int o = idx / (HH + WW);
            int l = idx - o * (HH + WW);
            float s = 0.f;
#pragma unroll
            for (int c = 0; c < CGC; c++) {
                float pv = (l < HH) ? __half2float(RSh[c * HH + l])
                                    : __half2float(CSh[c * WW + (l - HH)]);
                s += W1s[o * CGC + c] * pv;
            }
            float sg = sigm(B1s[o] + s * inv56);
            if (l < HH) XHh[o * HH + l] = __float2half_rn(sg);
            else        XWh[o * WW + (l - HH)] = __float2half_rn(sg);
        }
    }
    __syncthreads();

    // ---- Phase 3: per-channel total sum + stats of t = gx*xh*xw (warp per channel, x2) ----
    for (int c = warp; c < CGC; c += 8) {
        float v = __half2float(RSh[c * HH + lane]) +
                  ((lane < 24) ? __half2float(RSh[c * HH + 32 + lane]) : 0.f);
        v = wred(v);
        if (lane == 0) TT[c] = v;

        int sub = lane >> 4;
        int l16 = lane & 15;
        bool act = (l16 < 14);
        int xqe = act ? l16 : 13;
        float4 xw4 = h4tof4(*(const uint2*)(XWh + c * WW + xqe * 4));
        float4 s4 = make_float4(0.f, 0.f, 0.f, 0.f);
        float4 q4 = make_float4(0.f, 0.f, 0.f, 0.f);
        const __half* chb = SXH + c * HWP;
#pragma unroll 4
        for (int hh = 0; hh < 28; hh++) {
            int y = hh * 2 + sub;
            float hx = __half2float(XHh[c * HH + y]);
            float4 vv = h4tof4(*(const uint2*)(chb + y * WW + xqe * 4));
            if (act) {
                float t0 = vv.x * hx * xw4.x, t1 = vv.y * hx * xw4.y;
                float t2 = vv.z * hx * xw4.z, t3 = vv.w * hx * xw4.w;
                s4.x += t0; s4.y += t1; s4.z += t2; s4.w += t3;
                q4.x += t0 * t0; q4.y += t1 * t1; q4.z += t2 * t2; q4.w += t3 * t3;
            }
        }
        float sum = (s4.x + s4.y) + (s4.z + s4.w);
        float sq  = (q4.x + q4.y) + (q4.z + q4.w);
        sum = wred(sum); sq = wred(sq);
        if (lane == 0) {
            const float invhw = 1.f / (float)HWP;
            float mu = sum * invhw;
            float var = sq * invhw - mu * mu;
            if (var < 0.f) var = 0.f;
            float inv = rsqrtf(var + EPSV);
            MU[c] = mu;
            SSv[c] = inv * GNWs[c];
        }
    }
    __syncthreads();

    // ---- Phase 3b step1: shifted sums SA; a1 = softmax(gn_b); constA ----
    if (tid < 144) {
        int i = tid / 9, k = tid - i * 9;
        int oy = k / 3 - 1, ox = k % 3 - 1;
        float S = TT[i];
        if (oy) S -= __half2float(RSh[i * HH + (oy < 0 ? HH - 1 : 0)]);
        if (ox) S -= __half2float(CSh[i * WW + (ox < 0 ? WW - 1 : 0)]);
        if (oy && ox) S += __half2float(SXH[i * HWP + (oy < 0 ? HH - 1 : 0) * WW + (ox < 0 ? WW - 1 : 0)]);
        SA[tid] = S;
    }
    if (tid == 150) {
        float mx = GNBs[0];
        for (int c = 1; c < CGC; c++) mx = fmaxf(mx, GNBs[c]);
        float ssum = 0.f;
        float e[CGC];
        for (int c = 0; c < CGC; c++) { e[c] = expf(GNBs[c] - mx); ssum += e[c]; }
        float cA = 0.f;
        for (int c = 0; c < CGC; c++) {
            float a = e[c] / ssum;
            A1v[c] = a;
            cA += a * B3s[c];
        }
        CONSTS[0] = cA;
    }
    __syncthreads();

    // ---- Phase 3b step2: collapsed conv weights (w3 from global/L2) + x2 channel means ----
    if (tid < 144) {
        int i = tid / 9, k = tid - i * 9;
        float s = 0.f;
#pragma unroll
        for (int o = 0; o < CGC; o++) s += A1v[o] * w3[o * 144 + tid];
        WCp[i * 12 + k] = s;
    }
    for (int o = warp; o < CGC; o += 8) {
        float m = 0.f;
        for (int j = lane; j < 144; j += 32) m += w3[o * 144 + j] * SA[j];
        m = wred(m);
        if (lane == 0) M2[o] = B3s[o] + m * (1.f / (float)HWP);
    }
    __syncthreads();

    // ---- Phase 3b step3: a2 softmax, per-channel coefs, const2 ----
    if (tid == 0) {
        float mx = M2[0];
        for (int c = 1; c < CGC; c++) mx = fmaxf(mx, M2[c]);
        float ssum = 0.f;
        float e[CGC];
        for (int c = 0; c < CGC; c++) { e[c] = expf(M2[c] - mx); ssum += e[c]; }
        float c2 = 0.f;
        for (int c = 0; c < CGC; c++) {
            float a = e[c] / ssum;
            float s = SSv[c];
            A2C[c] = a * s;
            c2 += a * (GNBs[c] - MU[c] * s);
        }
        CONSTS[1] = c2;
    }
    __syncthreads();

    // ---- Phase 5: fused weight map (4 output rows per unit) -> sigmoid -> output ----
    // 224 units: [rowblock(14 x 4rows)][lane16(16)], lanes >=14 and blocks >=14 idle.
    {
        const float wconst = CONSTS[0] + CONSTS[1];
        int blk = tid >> 4;
        int l16 = tid & 15;
        int blkc = (blk < 14) ? blk : 13;
        int y0 = blkc * 4;
        bool act = (blk < 14) && (l16 < 14);
        int xqe = (l16 < 14) ? l16 : 13;
        float mtop = (blkc > 0) ? 1.f : 0.f;
        float mbot = (blkc < 13) ? 1.f : 0.f;
        int kr0 = (blkc > 0) ? y0 - 1 : 0;
        int kr5 = (blkc < 13) ? y0 + 4 : 55;
        float4 acc0 = make_float4(wconst, wconst, wconst, wconst);
        float4 acc1 = acc0, acc2 = acc0, acc3 = acc0;
#pragma unroll 4
        for (int c = 0; c < CGC; c++) {
            const float* cw = WCp + c * 12;
            float4 wA = *(const float4*)cw;       // row0: x,y,z ; row1 starts at w
            float4 wB = *(const float4*)(cw + 4); // row1: (wA.w),x,y ; row2: z,w,(w8)
            float w8 = cw[8];
            float4 wv = h4tof4(*(const uint2*)(XWh + c * WW + xqe * 4));
            float a2c = A2C[c];
            const __half* xhp = XHh + c * HH + y0;
            float cf0 = a2c * __half2float(xhp[0]);
            float cf1 = a2c * __half2float(xhp[1]);
            float cf2 = a2c * __half2float(xhp[2]);
            float cf3 = a2c * __half2float(xhp[3]);
            const __half* chb = SXH + c * HWP;
            float4 Bv; float avw, cvx;
            GETROW(kr0, Bv, avw, cvx);            // row y0-1
            TAPS(acc0, wA.x * mtop, wA.y * mtop, wA.z * mtop, avw, Bv, cvx);
            GETROW(y0, Bv, avw, cvx);             // row y0
            TAPS(acc1, wA.x, wA.y, wA.z, avw, Bv, cvx);
            TAPS(acc0, wA.w, wB.x, wB.y, avw, Bv, cvx);
            acc0.x += cf0 * wv.x * Bv.x; acc0.y += cf0 * wv.y * Bv.y;
            acc0.z += cf0 * wv.z * Bv.z; acc0.w += cf0 * wv.w * Bv.w;
            GETROW(y0 + 1, Bv, avw, cvx);         // row y0+1
            TAPS(acc2, wA.x, wA.y, wA.z, avw, Bv, cvx);
            TAPS(acc1, wA.w, wB.x, wB.y, avw, Bv, cvx);
            TAPS(acc0, wB.z, wB.w, w8, avw, Bv, cvx);
            acc1.x += cf1 * wv.x * Bv.x; acc1.y += cf1 * wv.y * Bv.y;
            acc1.z += cf1 * wv.z * Bv.z; acc1.w += cf1 * wv.w * Bv.w;
            GETROW(y0 + 2, Bv, avw, cvx);         // row y0+2
            TAPS(acc3, wA.x, wA.y, wA.z, avw, Bv, cvx);
            TAPS(acc2, wA.w, wB.x, wB.y, avw, Bv, cvx);
            TAPS(acc1, wB.z, wB.w, w8, avw, Bv, cvx);
            acc2.x += cf2 * wv.x * Bv.x; acc2.y += cf2 * wv.y * Bv.y;
            acc2.z += cf2 * wv.z * Bv.z; acc2.w += cf2 * wv.w * Bv.w;
            GETROW(y0 + 3, Bv, avw, cvx);         // row y0+3
            TAPS(acc3, wA.w, wB.x, wB.y, avw, Bv, cvx);
            TAPS(acc2, wB.z, wB.w, w8, avw, Bv, cvx);
            acc3.x += cf3 * wv.x * Bv.x; acc3.y += cf3 * wv.y * Bv.y;
            acc3.z += cf3 * wv.z * Bv.z; acc3.w += cf3 * wv.w * Bv.w;
            GETROW(kr5, Bv, avw, cvx);            // row y0+4
            TAPS(acc3, wB.z * mbot, wB.w * mbot, w8 * mbot, avw, Bv, cvx);
        }
        if (act) {
            float4 s0, s1, s2, s3;
            s0.x = sigm(acc0.x); s0.y = sigm(acc0.y); s0.z = sigm(acc0.z); s0.w = sigm(acc0.w);
            s1.x = sigm(acc1.x); s1.y = sigm(acc1.y); s1.z = sigm(acc1.z); s1.w = sigm(acc1.w);
            s2.x = sigm(acc2.x); s2.y = sigm(acc2.y); s2.z = sigm(acc2.z); s2.w = sigm(acc2.w);
            s3.x = sigm(acc3.x); s3.y = sigm(acc3.y); s3.z = sigm(acc3.z); s3.w = sigm(acc3.w);
#pragma unroll 4
            for (int c = 0; c < CGC; c++) {
                const __half* sb = SXH + c * HWP + y0 * WW + xqe * 4;
                float* ob = og + c * HWP + y0 * WW + xqe * 4;
                float4 v0 = h4tof4(*(const uint2*)sb);
                float4 v1 = h4tof4(*(const uint2*)(sb + WW));
                float4 v2 = h4tof4(*(const uint2*)(sb + 2 * WW));
                float4 v3 = h4tof4(*(const uint2*)(sb + 3 * WW));
                float4 o0, o1, o2, o3;
                o0.x = v0.x * s0.x; o0.y = v0.y * s0.y; o0.z = v0.z * s0.z; o0.w = v0.w * s0.w;
                o1.x = v1.x * s1.x; o1.y = v1.y * s1.y; o1.z = v1.z * s1.z; o1.w = v1.w * s1.w;
                o2.x = v2.x * s2.x; o2.y = v2.y * s2.y; o2.z = v2.z * s2.z; o2.w = v2.w * s2.w;
                o3.x = v3.x * s3.x; o3.y = v3.y * s3.y; o3.z = v3.z * s3.z; o3.w = v3.w * s3.w;
                *(float4*)ob = o0;
                *(float4*)(ob + WW) = o1;
                *(float4*)(ob + 2 * WW) = o2;
                *(float4*)(ob + 3 * WW) = o3;
            }
        }
    }
}

extern "C" void kernel_launch(void* const* d_in, const int* in_sizes, int n_in,
                              void* d_out, int out_size) {
    const float* x   = (const float*)d_in[0];
    const float* w1  = (const float*)d_in[1];
    const float* b1  = (const float*)d_in[2];
    const float* w3  = (const float*)d_in[3];
    const float* b3  = (const float*)d_in[4];
    const float* gnw = (const float*)d_in[5];
    const float* gnb = (const float*)d_in[6];
    float* out = (float*)d_out;

    cudaFuncSetAttribute(ema_fused_kernel,
                         cudaFuncAttributeMaxDynamicSharedMemorySize, SMEM_BYTES);
    ema_fused_kernel<<<NGRP, NT, SMEM_BYTES>>>(x, w1, b1, w3, b3, gnw, gnb, out);
}

// round 7
// speedup vs baseline: 2.0011x; 1.0678x over previous
#include <cuda_runtime.h>
#include <cuda_fp16.h>
#include <cstdint>

#define HH 56
#define WW 56
#define HWP 3136
#define CGC 16
#define NGRP 1024
#define NT 512
#define EPSV 1e-5f

// byte offsets into dynamic smem
#define OB_SX    0        // fp16 tile 16*3136
#define OB_XH    100352   // fp16 16*56
#define OB_XW    102144
#define OB_RS    103936
#define OB_CS    105728
#define OB_W1    107520   // fp32 256
#define OB_WC    108544   // fp32 16*12
#define OB_SA    109312   // fp32 144
#define OB_B1    109888
#define OB_B3    109952
#define OB_GNW   110016
#define OB_GNB   110080
#define OB_MU    110144
#define OB_SS    110208
#define OB_TT    110272
#define OB_M2    110336
#define OB_A1    110400
#define OB_A2C   110464
#define OB_CONST 110528
#define SMEM_BYTES 110592

__device__ __forceinline__ float wred(float v) {
#pragma unroll
    for (int o = 16; o; o >>= 1) v += __shfl_down_sync(0xffffffffu, v, o);
    return v;
}
__device__ __forceinline__ float sigm(float z) { return 1.f / (1.f + __expf(-z)); }

__device__ __forceinline__ float4 h4tof4(uint2 u) {
    __half2 a = *reinterpret_cast<__half2*>(&u.x);
    __half2 b = *reinterpret_cast<__half2*>(&u.y);
    float2 fa = __half22float2(a), fb = __half22float2(b);
    return make_float4(fa.x, fa.y, fb.x, fb.y);
}

#define TAPS(acc, t0, t1, t2, avw, Bv, cvx) do { \
    acc.x += (t0) * (avw) + (t1) * Bv.x + (t2) * Bv.y; \
    acc.y += (t0) * Bv.x  + (t1) * Bv.y + (t2) * Bv.z; \
    acc.z += (t0) * Bv.y  + (t1) * Bv.z + (t2) * Bv.w; \
    acc.w += (t0) * Bv.z  + (t1) * Bv.w + (t2) * (cvx); } while (0)

#define GETROW(ry, Bv, avw, cvx) do { \
    Bv = h4tof4(*(const uint2*)(chb + (ry) * WW + xqe * 4)); \
    avw = __shfl_up_sync(0xffffffffu, Bv.w, 1, 16); \
    cvx = __shfl_down_sync(0xffffffffu, Bv.x, 1, 16); \
    if (l16 == 0) avw = 0.f; \
    if (l16 == 13) cvx = 0.f; } while (0)

__global__ __launch_bounds__(NT, 2)
void ema_fused_kernel(const float* __restrict__ x,
                      const float* __restrict__ w1, const float* __restrict__ b1,
                      const float* __restrict__ w3, const float* __restrict__ b3,
                      const float* __restrict__ gnw, const float* __restrict__ gnb,
                      float* __restrict__ out) {
    extern __shared__ char smc[];
    __half* SXH = (__half*)(smc + OB_SX);
    __half* XHh = (__half*)(smc + OB_XH);
    __half* XWh = (__half*)(smc + OB_XW);
    __half* RSh = (__half*)(smc + OB_RS);
    __half* CSh = (__half*)(smc + OB_CS);
    float* W1s = (float*)(smc + OB_W1);
    float* WCp = (float*)(smc + OB_WC);
    float* SA  = (float*)(smc + OB_SA);
    float* B1s = (float*)(smc + OB_B1);
    float* B3s = (float*)(smc + OB_B3);
    float* GNWs = (float*)(smc + OB_GNW);
    float* GNBs = (float*)(smc + OB_GNB);
    float* MU  = (float*)(smc + OB_MU);
    float* SSv = (float*)(smc + OB_SS);
    float* TT  = (float*)(smc + OB_TT);
    float* M2  = (float*)(smc + OB_M2);
    float* A1v = (float*)(smc + OB_A1);
    float* A2C = (float*)(smc + OB_A2C);
    float* CONSTS = (float*)(smc + OB_CONST);

    const int tid = threadIdx.x;
    const int g = blockIdx.x;
    const float* gx = x + (size_t)g * (CGC * HWP);
    float* og = out + (size_t)g * (CGC * HWP);

    const int warp = tid >> 5;
    const int lane = tid & 31;

    // ---- Phase 0: load tile (fp32 -> fp16) + params ----
    {
        const float4* gx4 = (const float4*)gx;
#pragma unroll 4
        for (int i = tid; i < (CGC * HWP) / 4; i += NT) {
            float4 v = gx4[i];
            __half2 h0 = __floats2half2_rn(v.x, v.y);
            __half2 h1 = __floats2half2_rn(v.z, v.w);
            uint2 u;
            u.x = *(unsigned int*)&h0;
            u.y = *(unsigned int*)&h1;
            *(uint2*)(SXH + i * 4) = u;
        }
        if (tid < 256) W1s[tid] = w1[tid];
        if (tid < 16) {
            B1s[tid] = b1[tid]; B3s[tid] = b3[tid];
            GNWs[tid] = gnw[tid]; GNBs[tid] = gnb[tid];
        }
    }
    __syncthreads();

    // ---- Phase 1a: row sums (thread per row, uint4 of 8 halfs) ----
    for (int r = tid; r < CGC * HH; r += NT) {
        const uint4* row = (const uint4*)(SXH + r * WW);
        float s = 0.f;
#pragma unroll
        for (int j = 0; j < 7; j++) {
            uint4 u = row[j];
            float4 a = h4tof4(make_uint2(u.x, u.y));
            float4 b = h4tof4(make_uint2(u.z, u.w));
            s += (a.x + a.y) + (a.z + a.w) + (b.x + b.y) + (b.z + b.w);
        }
        RSh[r] = __float2half_rn(s);
    }
    // ---- Phase 1b: col sums ----
    for (int t = tid; t < CGC * WW; t += NT) {
        int c = t / WW, xp = t - c * WW;
        const __half* base = SXH + c * HWP + xp;
        float sA = 0.f, sB = 0.f;
#pragma unroll 8
        for (int y = 0; y < HH; y += 2) {
            sA += __half2float(base[y * WW]);
            sB += __half2float(base[(y + 1) * WW]);
        }
        CSh[t] = __float2half_rn(sA + sB);
    }
    __syncthreads();

    // ---- Phase 2: conv1x1 channel mix + sigmoid -> XH, XW ----
    {
        const float inv56 = 1.f / 56.f;
        for (int idx = tid; idx < CGC * (HH + WW); idx += NT) {
            int o = idx / (HH + WW);
            int l = idx - o * (HH + WW);
            float s = 0.f;
#pragma unroll
            for (int c = 0; c < CGC; c++) {
                float pv = (l < HH) ? __half2float(RSh[c * HH + l])
                                    : __half2float(CSh[c * WW + (l - HH)]);
                s += W1s[o * CGC + c] * pv;
            }
            float sg = sigm(B1s[o] + s * inv56);
            if (l < HH) XHh[o * HH + l] = __float2half_rn(sg);
            else        XWh[o * WW + (l - HH)] = __float2half_rn(sg);
        }
    }
    __syncthreads();

    // ---- Phase 3: per-channel total sum + stats of t = gx*xh*xw (warp per channel) ----
    {
        int c = warp;  // 16 warps == 16 channels
        float v = __half2float(RSh[c * HH + lane]) +
                  ((lane < 24) ? __half2float(RSh[c * HH + 32 + lane]) : 0.f);
        v = wred(v);
        if (lane == 0) TT[c] = v;

        int sub = lane >> 4;
        int l16 = lane & 15;
        bool act = (l16 < 14);
        int xqe = act ? l16 : 13;
        float4 xw4 = h4tof4(*(const uint2*)(XWh + c * WW + xqe * 4));
        float4 s4 = make_float4(0.f, 0.f, 0.f, 0.f);
        float4 q4 = make_float4(0.f, 0.f, 0.f, 0.f);
        const __half* chb = SXH + c * HWP;
#pragma unroll 4
        for (int hh = 0; hh < 28; hh++) {
            int y = hh * 2 + sub;
            float hx = __half2float(XHh[c * HH + y]);
            float4 vv = h4tof4(*(const uint2*)(chb + y * WW + xqe * 4));
            if (act) {
                float t0 = vv.x * hx * xw4.x, t1 = vv.y * hx * xw4.y;
                float t2 = vv.z * hx * xw4.z, t3 = vv.w * hx * xw4.w;
                s4.x += t0; s4.y += t1; s4.z += t2; s4.w += t3;
                q4.x += t0 * t0; q4.y += t1 * t1; q4.z += t2 * t2; q4.w += t3 * t3;
            }
        }
        float sum = (s4.x + s4.y) + (s4.z + s4.w);
        float sq  = (q4.x + q4.y) + (q4.z + q4.w);
        sum = wred(sum); sq = wred(sq);
        if (lane == 0) {
            const float invhw = 1.f / (float)HWP;
            float mu = sum * invhw;
            float var = sq * invhw - mu * mu;
            if (var < 0.f) var = 0.f;
            float inv = rsqrtf(var + EPSV);
            MU[c] = mu;
            SSv[c] = inv * GNWs[c];
        }
    }
    __syncthreads();

    // ---- Phase 3b step1: shifted sums SA; a1 = softmax(gn_b); constA ----
    if (tid < 144) {
        int i = tid / 9, k = tid - i * 9;
        int oy = k / 3 - 1, ox = k % 3 - 1;
        float S = TT[i];
        if (oy) S -= __half2float(RSh[i * HH + (oy < 0 ? HH - 1 : 0)]);
        if (ox) S -= __half2float(CSh[i * WW + (ox < 0 ? WW - 1 : 0)]);
        if (oy && ox) S += __half2float(SXH[i * HWP + (oy < 0 ? HH - 1 : 0) * WW + (ox < 0 ? WW - 1 : 0)]);
        SA[tid] = S;
    }
    if (tid == 160) {
        float mx = GNBs[0];
        for (int c = 1; c < CGC; c++) mx = fmaxf(mx, GNBs[c]);
        float ssum = 0.f;
        float e[CGC];
        for (int c = 0; c < CGC; c++) { e[c] = expf(GNBs[c] - mx); ssum += e[c]; }
        float cA = 0.f;
        for (int c = 0; c < CGC; c++) {
            float a = e[c] / ssum;
            A1v[c] = a;
            cA += a * B3s[c];
        }
        CONSTS[0] = cA;
    }
    __syncthreads();

    // ---- Phase 3b step2: collapsed conv weights (w3 via L2) + x2 channel means ----
    if (tid < 144) {
        int i = tid / 9, k = tid - i * 9;
        float s = 0.f;
#pragma unroll
        for (int o = 0; o < CGC; o++) s += A1v[o] * w3[o * 144 + tid];
        WCp[i * 12 + k] = s;
    }
    {
        int o = warp;  // 16 warps == 16 output channels
        float m = 0.f;
        for (int j = lane; j < 144; j += 32) m += w3[o * 144 + j] * SA[j];
        m = wred(m);
        if (lane == 0) M2[o] = B3s[o] + m * (1.f / (float)HWP);
    }
    __syncthreads();

    // ---- Phase 3b step3: a2 softmax, per-channel coefs, const2 ----
    if (tid == 0) {
        float mx = M2[0];
        for (int c = 1; c < CGC; c++) mx = fmaxf(mx, M2[c]);
        float ssum = 0.f;
        float e[CGC];
        for (int c = 0; c < CGC; c++) { e[c] = expf(M2[c] - mx); ssum += e[c]; }
        float c2 = 0.f;
        for (int c = 0; c < CGC; c++) {
            float a = e[c] / ssum;
            float s = SSv[c];
            A2C[c] = a * s;
            c2 += a * (GNBs[c] - MU[c] * s);
        }
        CONSTS[1] = c2;
    }
    __syncthreads();

    // ---- Phase 5: fused weight map (2 output rows per unit) -> sigmoid -> output ----
    // 32 blocks of 16 lanes; 28 blocks active, y0 = blk*2.
    {
        const float wconst = CONSTS[0] + CONSTS[1];
        int blk = tid >> 4;
        int l16 = tid & 15;
        int blkc = (blk < 28) ? blk : 27;
        int y0 = blkc * 2;
        bool act = (blk < 28) && (l16 < 14);
        int xqe = (l16 < 14) ? l16 : 13;
        float mtop = (blkc > 0) ? 1.f : 0.f;
        float mbot = (blkc < 27) ? 1.f : 0.f;
        int krT = (blkc > 0) ? y0 - 1 : 0;
        int krB = (blkc < 27) ? y0 + 2 : 55;
        float4 acc0 = make_float4(wconst, wconst, wconst, wconst);
        float4 acc1 = acc0;
#pragma unroll 4
        for (int c = 0; c < CGC; c++) {
            const float* cw = WCp + c * 12;
            float4 wA = *(const float4*)cw;       // taps 0..3
            float4 wB = *(const float4*)(cw + 4); // taps 4..7
            float w8 = cw[8];
            float4 wv = h4tof4(*(const uint2*)(XWh + c * WW + xqe * 4));
            float a2c = A2C[c];
            const __half* xhp = XHh + c * HH + y0;
            float cf0 = a2c * __half2float(xhp[0]);
            float cf1 = a2c * __half2float(xhp[1]);
            const __half* chb = SXH + c * HWP;
            float4 Bv; float avw, cvx;
            GETROW(krT, Bv, avw, cvx);            // row y0-1 (masked)
            TAPS(acc0, wA.x * mtop, wA.y * mtop, wA.z * mtop, avw, Bv, cvx);
            GETROW(y0, Bv, avw, cvx);             // row y0
            TAPS(acc0, wA.w, wB.x, wB.y, avw, Bv, cvx);
            TAPS(acc1, wA.x, wA.y, wA.z, avw, Bv, cvx);
            acc0.x += cf0 * wv.x * Bv.x; acc0.y += cf0 * wv.y * Bv.y;
            acc0.z += cf0 * wv.z * Bv.z; acc0.w += cf0 * wv.w * Bv.w;
            GETROW(y0 + 1, Bv, avw, cvx);         // row y0+1
            TAPS(acc0, wB.z, wB.w, w8, avw, Bv, cvx);
            TAPS(acc1, wA.w, wB.x, wB.y, avw, Bv, cvx);
            acc1.x += cf1 * wv.x * Bv.x; acc1.y += cf1 * wv.y * Bv.y;
            acc1.z += cf1 * wv.z * Bv.z; acc1.w += cf1 * wv.w * Bv.w;
            GETROW(krB, Bv, avw, cvx);            // row y0+2 (masked)
            TAPS(acc1, wB.z * mbot, wB.w * mbot, w8 * mbot, avw, Bv, cvx);
        }
        if (act) {
            float4 s0, s1;
            s0.x = sigm(acc0.x); s0.y = sigm(acc0.y); s0.z = sigm(acc0.z); s0.w = sigm(acc0.w);
            s1.x = sigm(acc1.x); s1.y = sigm(acc1.y); s1.z = sigm(acc1.z); s1.w = sigm(acc1.w);
#pragma unroll 4
            for (int c = 0; c < CGC; c++) {
                const __half* sb = SXH + c * HWP + y0 * WW + xqe * 4;
                float* ob = og + c * HWP + y0 * WW + xqe * 4;
                float4 v0 = h4tof4(*(const uint2*)sb);
                float4 v1 = h4tof4(*(const uint2*)(sb + WW));
                float4 o0, o1;
                o0.x = v0.x * s0.x; o0.y = v0.y * s0.y; o0.z = v0.z * s0.z; o0.w = v0.w * s0.w;
                o1.x = v1.x * s1.x; o1.y = v1.y * s1.y; o1.z = v1.z * s1.z; o1.w = v1.w * s1.w;
                *(float4*)ob = o0;
                *(float4*)(ob + WW) = o1;
            }
        }
    }
}

extern "C" void kernel_launch(void* const* d_in, const int* in_sizes, int n_in,
                              void* d_out, int out_size) {
    const float* x   = (const float*)d_in[0];
    const float* w1  = (const float*)d_in[1];
    const float* b1  = (const float*)d_in[2];
    const float* w3  = (const float*)d_in[3];
    const float* b3  = (const float*)d_in[4];
    const float* gnw = (const float*)d_in[5];
    const float* gnb = (const float*)d_in[6];
    float* out = (float*)d_out;

    cudaFuncSetAttribute(ema_fused_kernel,
                         cudaFuncAttributeMaxDynamicSharedMemorySize, SMEM_BYTES);
    ema_fused_kernel<<<NGRP, NT, SMEM_BYTES>>>(x, w1, b1, w3, b3, gnw, gnb, out);
}

// round 8
// speedup vs baseline: 2.1008x; 1.0498x over previous
#include <cuda_runtime.h>
#include <cuda_fp16.h>
#include <cstdint>

#define HH 56
#define WW 56
#define HWP 3136
#define CGC 16
#define NGRP 1024
#define NT 512
#define EPSV 1e-5f

// byte offsets into dynamic smem
#define OB_SX    0        // fp16 tile 16*3136
#define OB_XH    100352   // fp16 16*56
#define OB_XW    102144
#define OB_RS    103936
#define OB_CS    105728
#define OB_W1    107520   // fp32 256
#define OB_WC    108544   // fp32 16*12
#define OB_SA    109312   // fp32 144
#define OB_B1    109888
#define OB_B3    109952
#define OB_GNW   110016
#define OB_GNB   110080
#define OB_MU    110144
#define OB_SS    110208
#define OB_TT    110272
#define OB_M2    110336
#define OB_A1    110400
#define OB_A2C   110464
#define OB_CONST 110528
#define SMEM_BYTES 110592

__device__ __forceinline__ float wred(float v) {
#pragma unroll
    for (int o = 16; o; o >>= 1) v += __shfl_down_sync(0xffffffffu, v, o);
    return v;
}
__device__ __forceinline__ float sigm(float z) { return 1.f / (1.f + __expf(-z)); }

__device__ __forceinline__ float4 h4tof4(uint2 u) {
    __half2 a = *reinterpret_cast<__half2*>(&u.x);
    __half2 b = *reinterpret_cast<__half2*>(&u.y);
    float2 fa = __half22float2(a), fb = __half22float2(b);
    return make_float4(fa.x, fa.y, fb.x, fb.y);
}

#define TAPS(acc, t0, t1, t2, avw, Bv, cvx) do { \
    acc.x += (t0) * (avw) + (t1) * Bv.x + (t2) * Bv.y; \
    acc.y += (t0) * Bv.x  + (t1) * Bv.y + (t2) * Bv.z; \
    acc.z += (t0) * Bv.y  + (t1) * Bv.z + (t2) * Bv.w; \
    acc.w += (t0) * Bv.z  + (t1) * Bv.w + (t2) * (cvx); } while (0)

#define GETROW(ry, Bv, avw, cvx) do { \
    Bv = h4tof4(*(const uint2*)(chb + (ry) * WW + xqe * 4)); \
    avw = __shfl_up_sync(0xffffffffu, Bv.w, 1, 16); \
    cvx = __shfl_down_sync(0xffffffffu, Bv.x, 1, 16); \
    if (l16 == 0) avw = 0.f; \
    if (l16 == 13) cvx = 0.f; } while (0)

__global__ __launch_bounds__(NT, 2)
void ema_fused_kernel(const float* __restrict__ x,
                      const float* __restrict__ w1, const float* __restrict__ b1,
                      const float* __restrict__ w3, const float* __restrict__ b3,
                      const float* __restrict__ gnw, const float* __restrict__ gnb,
                      float* __restrict__ out) {
    extern __shared__ char smc[];
    __half* SXH = (__half*)(smc + OB_SX);
    __half* XHh = (__half*)(smc + OB_XH);
    __half* XWh = (__half*)(smc + OB_XW);
    __half* RSh = (__half*)(smc + OB_RS);
    __half* CSh = (__half*)(smc + OB_CS);
    float* W1s = (float*)(smc + OB_W1);
    float* WCp = (float*)(smc + OB_WC);
    float* SA  = (float*)(smc + OB_SA);
    float* B1s = (float*)(smc + OB_B1);
    float* B3s = (float*)(smc + OB_B3);
    float* GNWs = (float*)(smc + OB_GNW);
    float* GNBs = (float*)(smc + OB_GNB);
    float* MU  = (float*)(smc + OB_MU);
    float* SSv = (float*)(smc + OB_SS);
    float* TT  = (float*)(smc + OB_TT);
    float* M2  = (float*)(smc + OB_M2);
    float* A1v = (float*)(smc + OB_A1);
    float* A2C = (float*)(smc + OB_A2C);
    float* CONSTS = (float*)(smc + OB_CONST);

    const int tid = threadIdx.x;
    const int g = blockIdx.x;
    const float* gx = x + (size_t)g * (CGC * HWP);
    float* og = out + (size_t)g * (CGC * HWP);

    const int warp = tid >> 5;
    const int lane = tid & 31;

    // ---- Phase 0: load tile (fp32 -> fp16) + params ----
    {
        const float4* gx4 = (const float4*)gx;
#pragma unroll 4
        for (int i = tid; i < (CGC * HWP) / 4; i += NT) {
            float4 v = gx4[i];
            __half2 h0 = __floats2half2_rn(v.x, v.y);
            __half2 h1 = __floats2half2_rn(v.z, v.w);
            uint2 u;
            u.x = *(unsigned int*)&h0;
            u.y = *(unsigned int*)&h1;
            *(uint2*)(SXH + i * 4) = u;
        }
        if (tid < 256) W1s[tid] = w1[tid];
        if (tid < 16) {
            B1s[tid] = b1[tid]; B3s[tid] = b3[tid];
            GNWs[tid] = gnw[tid]; GNBs[tid] = gnb[tid];
        }
    }
    __syncthreads();

    // ---- Phase 1a: row sums (thread per row, uint4 of 8 halfs) ----
    for (int r = tid; r < CGC * HH; r += NT) {
        const uint4* row = (const uint4*)(SXH + r * WW);
        float s = 0.f;
#pragma unroll
        for (int j = 0; j < 7; j++) {
            uint4 u = row[j];
            float4 a = h4tof4(make_uint2(u.x, u.y));
            float4 b = h4tof4(make_uint2(u.z, u.w));
            s += (a.x + a.y) + (a.z + a.w) + (b.x + b.y) + (b.z + b.w);
        }
        RSh[r] = __float2half_rn(s);
    }
    // ---- Phase 1b: col sums, half2 pair per thread ----
    if (tid < 448) {
        int c = tid / 28, xq = tid - c * 28;
        const __half* base = SXH + c * HWP + xq * 2;
        float sA = 0.f, sB = 0.f;
#pragma unroll 8
        for (int y = 0; y < HH; y++) {
            __half2 hv = *(const __half2*)(base + y * WW);
            float2 f = __half22float2(hv);
            sA += f.x; sB += f.y;
        }
        *(__half2*)(CSh + c * WW + xq * 2) = __floats2half2_rn(sA, sB);
    }
    __syncthreads();

    // ==== Merged Phase 2 (warp-per-channel conv1x1+sigmoid) + Phase 3 (stats) ====
    {
        const int o = warp;  // channel owned by this warp
        const float inv56 = 1.f / 56.f;
        for (int ii = lane; ii < HH + WW; ii += 32) {
            float s = 0.f;
#pragma unroll
            for (int c = 0; c < CGC; c++) {
                float pv = (ii < HH) ? __half2float(RSh[c * HH + ii])
                                     : __half2float(CSh[c * WW + (ii - HH)]);
                s += W1s[o * CGC + c] * pv;
            }
            float sg = sigm(B1s[o] + s * inv56);
            if (ii < HH) XHh[o * HH + ii] = __float2half_rn(sg);
            else         XWh[o * WW + (ii - HH)] = __float2half_rn(sg);
        }
        __syncwarp();

        // phase 3 stats for c = o (uses only this warp's XH/XW)
        const int c = o;
        float v = __half2float(RSh[c * HH + lane]) +
                  ((lane < 24) ? __half2float(RSh[c * HH + 32 + lane]) : 0.f);
        v = wred(v);
        if (lane == 0) TT[c] = v;

        int sub = lane >> 4;
        int l16 = lane & 15;
        bool act = (l16 < 14);
        int xqe = act ? l16 : 13;
        float4 xw4 = h4tof4(*(const uint2*)(XWh + c * WW + xqe * 4));
        float4 s4 = make_float4(0.f, 0.f, 0.f, 0.f);
        float4 q4 = make_float4(0.f, 0.f, 0.f, 0.f);
        const __half* chb = SXH + c * HWP;
#pragma unroll 4
        for (int hh = 0; hh < 28; hh++) {
            int y = hh * 2 + sub;
            float hx = __half2float(XHh[c * HH + y]);
            float4 vv = h4tof4(*(const uint2*)(chb + y * WW + xqe * 4));
            if (act) {
                float t0 = vv.x * hx * xw4.x, t1 = vv.y * hx * xw4.y;
                float t2 = vv.z * hx * xw4.z, t3 = vv.w * hx * xw4.w;
                s4.x += t0; s4.y += t1; s4.z += t2; s4.w += t3;
                q4.x += t0 * t0; q4.y += t1 * t1; q4.z += t2 * t2; q4.w += t3 * t3;
            }
        }
        float sum = (s4.x + s4.y) + (s4.z + s4.w);
        float sq  = (q4.x + q4.y) + (q4.z + q4.w);
        sum = wred(sum); sq = wred(sq);
        if (lane == 0) {
            const float invhw = 1.f / (float)HWP;
            float mu = sum * invhw;
            float var = sq * invhw - mu * mu;
            if (var < 0.f) var = 0.f;
            float inv = rsqrtf(var + EPSV);
            MU[c] = mu;
            SSv[c] = inv * GNWs[c];
        }
    }
    __syncthreads();

    // ---- 3bA: shifted sums SA (threads 256..399) || a1 softmax (lanes 0-15 of warp 0) ----
    if (tid >= 256 && tid < 400) {
        int idx = tid - 256;
        int i = idx / 9, k = idx - i * 9;
        int oy = k / 3 - 1, ox = k % 3 - 1;
        float S = TT[i];
        if (oy) S -= __half2float(RSh[i * HH + (oy < 0 ? HH - 1 : 0)]);
        if (ox) S -= __half2float(CSh[i * WW + (ox < 0 ? WW - 1 : 0)]);
        if (oy && ox) S += __half2float(SXH[i * HWP + (oy < 0 ? HH - 1 : 0) * WW + (ox < 0 ? WW - 1 : 0)]);
        SA[idx] = S;
    }
    if (tid < 16) {
        float gb = GNBs[tid];
        float mx = gb;
#pragma unroll
        for (int o = 8; o; o >>= 1) mx = fmaxf(mx, __shfl_xor_sync(0xffffu, mx, o, 16));
        float e = expf(gb - mx);
        float ssum = e;
#pragma unroll
        for (int o = 8; o; o >>= 1) ssum += __shfl_xor_sync(0xffffu, ssum, o, 16);
        float a = e / ssum;
        A1v[tid] = a;
        float cA = a * B3s[tid];
#pragma unroll
        for (int o = 8; o; o >>= 1) cA += __shfl_xor_sync(0xffffu, cA, o, 16);
        if (tid == 0) CONSTS[0] = cA;
    }
    __syncthreads();

    // ---- 3bB: collapsed conv weights (tid<144) || M2 dots (warps 8-15, 16 lanes per o) ----
    if (tid < 144) {
        int i = tid / 9, k = tid - i * 9;
        float s = 0.f;
#pragma unroll
        for (int o = 0; o < CGC; o++) s += A1v[o] * w3[o * 144 + tid];
        WCp[i * 12 + k] = s;
    }
    if (warp >= 8) {
        int o = (warp - 8) * 2 + (lane >> 4);
        int l16 = lane & 15;
        float m = 0.f;
#pragma unroll
        for (int j = l16; j < 144; j += 16) m += w3[o * 144 + j] * SA[j];
#pragma unroll
        for (int o2 = 8; o2; o2 >>= 1) m += __shfl_xor_sync(0xffffffffu, m, o2, 16);
        if (l16 == 0) M2[o] = B3s[o] + m * (1.f / (float)HWP);
    }
    __syncthreads();

    // ---- 3bC: a2 softmax + per-channel coefs (lanes 0-15) ----
    if (tid < 16) {
        float m2 = M2[tid];
        float mx = m2;
#pragma unroll
        for (int o = 8; o; o >>= 1) mx = fmaxf(mx, __shfl_xor_sync(0xffffu, mx, o, 16));
        float e = expf(m2 - mx);
        float ssum = e;
#pragma unroll
        for (int o = 8; o; o >>= 1) ssum += __shfl_xor_sync(0xffffu, ssum, o, 16);
        float a = e / ssum;
        float s = SSv[tid];
        A2C[tid] = a * s;
        float c2 = a * (GNBs[tid] - MU[tid] * s);
#pragma unroll
        for (int o = 8; o; o >>= 1) c2 += __shfl_xor_sync(0xffffu, c2, o, 16);
        if (tid == 0) CONSTS[1] = c2;
    }
    __syncthreads();

    // ---- Phase 5: fused weight map (2 output rows per unit) -> sigmoid -> output ----
    {
        const float wconst = CONSTS[0] + CONSTS[1];
        int blk = tid >> 4;
        int l16 = tid & 15;
        int blkc = (blk < 28) ? blk : 27;
        int y0 = blkc * 2;
        bool act = (blk < 28) && (l16 < 14);
        int xqe = (l16 < 14) ? l16 : 13;
        float mtop = (blkc > 0) ? 1.f : 0.f;
        float mbot = (blkc < 27) ? 1.f : 0.f;
        int krT = (blkc > 0) ? y0 - 1 : 0;
        int krB = (blkc < 27) ? y0 + 2 : 55;
        float4 acc0 = make_float4(wconst, wconst, wconst, wconst);
        float4 acc1 = acc0;
#pragma unroll 4
        for (int c = 0; c < CGC; c++) {
            const float* cw = WCp + c * 12;
            float4 wA = *(const float4*)cw;       // taps 0..3
            float4 wB = *(const float4*)(cw + 4); // taps 4..7
            float w8 = cw[8];
            float4 wv = h4tof4(*(const uint2*)(XWh + c * WW + xqe * 4));
            float a2c = A2C[c];
            float2 xh2 = __half22float2(*(const __half2*)(XHh + c * HH + y0));
            float cf0 = a2c * xh2.x;
            float cf1 = a2c * xh2.y;
            const __half* chb = SXH + c * HWP;
            float4 Bv; float avw, cvx;
            GETROW(krT, Bv, avw, cvx);            // row y0-1 (masked)
            TAPS(acc0, wA.x * mtop, wA.y * mtop, wA.z * mtop, avw, Bv, cvx);
            GETROW(y0, Bv, avw, cvx);             // row y0
            TAPS(acc0, wA.w, wB.x, wB.y, avw, Bv, cvx);
            TAPS(acc1, wA.x, wA.y, wA.z, avw, Bv, cvx);
            acc0.x += cf0 * wv.x * Bv.x; acc0.y += cf0 * wv.y * Bv.y;
            acc0.z += cf0 * wv.z * Bv.z; acc0.w += cf0 * wv.w * Bv.w;
            GETROW(y0 + 1, Bv, avw, cvx);         // row y0+1
            TAPS(acc0, wB.z, wB.w, w8, avw, Bv, cvx);
            TAPS(acc1, wA.w, wB.x, wB.y, avw, Bv, cvx);
            acc1.x += cf1 * wv.x * Bv.x; acc1.y += cf1 * wv.y * Bv.y;
            acc1.z += cf1 * wv.z * Bv.z; acc1.w += cf1 * wv.w * Bv.w;
            GETROW(krB, Bv, avw, cvx);            // row y0+2 (masked)
            TAPS(acc1, wB.z * mbot, wB.w * mbot, w8 * mbot, avw, Bv, cvx);
        }
        if (act) {
            float4 s0, s1;
            s0.x = sigm(acc0.x); s0.y = sigm(acc0.y); s0.z = sigm(acc0.z); s0.w = sigm(acc0.w);
            s1.x = sigm(acc1.x); s1.y = sigm(acc1.y); s1.z = sigm(acc1.z); s1.w = sigm(acc1.w);
#pragma unroll 4
            for (int c = 0; c < CGC; c++) {
                const __half* sb = SXH + c * HWP + y0 * WW + xqe * 4;
                float* ob = og + c * HWP + y0 * WW + xqe * 4;
                float4 v0 = h4tof4(*(const uint2*)sb);
                float4 v1 = h4tof4(*(const uint2*)(sb + WW));
                float4 o0, o1;
                o0.x = v0.x * s0.x; o0.y = v0.y * s0.y; o0.z = v0.z * s0.z; o0.w = v0.w * s0.w;
                o1.x = v1.x * s1.x; o1.y = v1.y * s1.y; o1.z = v1.z * s1.z; o1.w = v1.w * s1.w;
                *(float4*)ob = o0;
                *(float4*)(ob + WW) = o1;
            }
        }
    }
}

extern "C" void kernel_launch(void* const* d_in, const int* in_sizes, int n_in,
                              void* d_out, int out_size) {
    const float* x   = (const float*)d_in[0];
    const float* w1  = (const float*)d_in[1];
    const float* b1  = (const float*)d_in[2];
    const float* w3  = (const float*)d_in[3];
    const float* b3  = (const float*)d_in[4];
    const float* gnw = (const float*)d_in[5];
    const float* gnb = (const float*)d_in[6];
    float* out = (float*)d_out;

    cudaFuncSetAttribute(ema_fused_kernel,
                         cudaFuncAttributeMaxDynamicSharedMemorySize, SMEM_BYTES);
    ema_fused_kernel<<<NGRP, NT, SMEM_BYTES>>>(x, w1, b1, w3, b3, gnw, gnb, out);
}